// round 3
// baseline (speedup 1.0000x reference)
#include <cuda_runtime.h>

// ---------------------------------------------------------------------------
// QRN: 3-layer bidirectional quasi-RNN, T=65536, D=256.
// Per layer-direction:
//   z  = sigmoid((x*q) @ Wz + bz)
//   ht = tanh(x @ Wh[0:D] + q @ Wh[D:2D] + bh)
//   a = 1-z ; b = z*ht ; h_t = a_t * h_{t-1} + b_t  (scan)
// Backward direction == same GEMMs (forward order) + reversed scan.
// Output: h_fwd[T-1] of last layer (layer-2 backward pass is dead code).
// ---------------------------------------------------------------------------

#define TT 65536
#define DD 256
#define LL 3
#define BM 64
#define BN 64
#define BK 32
#define APAD 4
#define CH 256
#define NC (TT / CH)

// Scratch (device globals: no allocation allowed in kernel_launch)
__device__ float g_q[TT * DD];     // per-step question for current layer
__device__ float g_a[TT * DD];     // a = 1 - z
__device__ float g_b[TT * DD];     // b = z * h_tilde
__device__ float g_hf[TT * DD];    // forward hidden states of current layer
__device__ float g_Aagg[NC * DD];  // per-chunk scan aggregates
__device__ float g_Bagg[NC * DD];
__device__ float g_pref[NC * DD];  // per-chunk incoming prefix state

// ---- packed f32x2 helpers (FFMA2 path, sm_100+) ----
__device__ __forceinline__ unsigned long long pack2(float v) {
    unsigned long long r;
    asm("mov.b64 %0, {%1, %1};" : "=l"(r) : "f"(v));
    return r;
}
__device__ __forceinline__ unsigned long long ffma2(unsigned long long a,
                                                    unsigned long long b,
                                                    unsigned long long c) {
    unsigned long long d;
    asm("fma.rn.f32x2 %0, %1, %2, %3;" : "=l"(d) : "l"(a), "l"(b), "l"(c));
    return d;
}
__device__ __forceinline__ float2 unpack2(unsigned long long v) {
    float2 f;
    asm("mov.b64 {%0, %1}, %2;" : "=f"(f.x), "=f"(f.y) : "l"(v));
    return f;
}

__device__ __forceinline__ float fast_sigmoid(float x) {
    return 1.0f / (1.0f + __expf(-x));
}
__device__ __forceinline__ float fast_tanh(float x) {
    // 1 - 2/(e^{2x}+1): correct saturation at both ends (no inf/inf)
    return 1.0f - 2.0f / (__expf(2.0f * x) + 1.0f);
}

// ---------------------------------------------------------------------------
// Fused GEMM: computes z-preact and h-preact tiles simultaneously, applies
// sigmoid/tanh gating, writes a = 1-z and b = z*ht.
// Tile: 64x64, K-step 32, 256 threads, 4x4 outputs/thread (f32x2 along n).
// ---------------------------------------------------------------------------
__global__ __launch_bounds__(256, 2) void qrn_gemm(
    const float* __restrict__ x,
    const float* __restrict__ Wz, const float* __restrict__ bz,
    const float* __restrict__ Wh, const float* __restrict__ bh) {
    __shared__ float sX[BK][BM + APAD];
    __shared__ float sQ[BK][BM + APAD];
    __shared__ float sWz[BK][BN];
    __shared__ float sWt[BK][BN];
    __shared__ float sWb[BK][BN];

    const int tid = threadIdx.x;
    const int tx = tid & 15;   // col group (4 cols)
    const int ty = tid >> 4;   // row group (4 rows)
    const int row0 = blockIdx.x * BM;
    const int col0 = blockIdx.y * BN;
    const float* __restrict__ q = g_q;
    const float* __restrict__ Wht = Wh;            // rows 0..D-1   (x part)
    const float* __restrict__ Whb = Wh + DD * DD;  // rows D..2D-1  (q part)

    unsigned long long accz[4][2], acch[4][2];
#pragma unroll
    for (int i = 0; i < 4; i++) {
        accz[i][0] = 0ull; accz[i][1] = 0ull;
        acch[i][0] = 0ull; acch[i][1] = 0ull;
    }

    for (int k0 = 0; k0 < DD; k0 += BK) {
        // A tiles (x, q), stored transposed [k][m]
#pragma unroll
        for (int l = 0; l < 2; l++) {
            int s = tid + l * 256;
            int m = s >> 3;
            int kk = (s & 7) << 2;
            const float4 vx = *(const float4*)&x[(row0 + m) * DD + k0 + kk];
            const float4 vq = *(const float4*)&q[(row0 + m) * DD + k0 + kk];
            sX[kk + 0][m] = vx.x; sX[kk + 1][m] = vx.y;
            sX[kk + 2][m] = vx.z; sX[kk + 3][m] = vx.w;
            sQ[kk + 0][m] = vq.x; sQ[kk + 1][m] = vq.y;
            sQ[kk + 2][m] = vq.z; sQ[kk + 3][m] = vq.w;
        }
        // B tiles (Wz, Wh_top, Wh_bot), natural [k][n]
#pragma unroll
        for (int l = 0; l < 2; l++) {
            int s = tid + l * 256;
            int k = s >> 4;
            int n4 = (s & 15) << 2;
            *(float4*)&sWz[k][n4] = *(const float4*)&Wz[(k0 + k) * DD + col0 + n4];
            *(float4*)&sWt[k][n4] = *(const float4*)&Wht[(k0 + k) * DD + col0 + n4];
            *(float4*)&sWb[k][n4] = *(const float4*)&Whb[(k0 + k) * DD + col0 + n4];
        }
        __syncthreads();
#pragma unroll
        for (int k = 0; k < BK; k++) {
            float4 xf = *(const float4*)&sX[k][ty << 2];
            float4 qf = *(const float4*)&sQ[k][ty << 2];
            ulonglong2 wz = *(const ulonglong2*)&sWz[k][tx << 2];
            ulonglong2 wt = *(const ulonglong2*)&sWt[k][tx << 2];
            ulonglong2 wb = *(const ulonglong2*)&sWb[k][tx << 2];
            const float xs[4] = {xf.x, xf.y, xf.z, xf.w};
            const float qs[4] = {qf.x, qf.y, qf.z, qf.w};
#pragma unroll
            for (int i = 0; i < 4; i++) {
                unsigned long long X2 = pack2(xs[i]);
                unsigned long long Q2 = pack2(qs[i]);
                unsigned long long XQ2 = pack2(xs[i] * qs[i]);
                accz[i][0] = ffma2(XQ2, wz.x, accz[i][0]);
                accz[i][1] = ffma2(XQ2, wz.y, accz[i][1]);
                acch[i][0] = ffma2(X2, wt.x, acch[i][0]);
                acch[i][1] = ffma2(X2, wt.y, acch[i][1]);
                acch[i][0] = ffma2(Q2, wb.x, acch[i][0]);
                acch[i][1] = ffma2(Q2, wb.y, acch[i][1]);
            }
        }
        __syncthreads();
    }

    // Epilogue: gate + write a, b
    const float4 bz4 = *(const float4*)&bz[col0 + (tx << 2)];
    const float4 bh4 = *(const float4*)&bh[col0 + (tx << 2)];
#pragma unroll
    for (int i = 0; i < 4; i++) {
        float2 z01 = unpack2(accz[i][0]);
        float2 z23 = unpack2(accz[i][1]);
        float2 h01 = unpack2(acch[i][0]);
        float2 h23 = unpack2(acch[i][1]);
        float zp[4] = {z01.x + bz4.x, z01.y + bz4.y, z23.x + bz4.z, z23.y + bz4.w};
        float hp[4] = {h01.x + bh4.x, h01.y + bh4.y, h23.x + bh4.z, h23.y + bh4.w};
        float4 av, bv;
        float* avp = &av.x;
        float* bvp = &bv.x;
#pragma unroll
        for (int j = 0; j < 4; j++) {
            float z = fast_sigmoid(zp[j]);
            float ht = fast_tanh(hp[j]);
            avp[j] = 1.0f - z;
            bvp[j] = z * ht;
        }
        const int gm = row0 + (ty << 2) + i;
        *(float4*)&g_a[gm * DD + col0 + (tx << 2)] = av;
        *(float4*)&g_b[gm * DD + col0 + (tx << 2)] = bv;
    }
}

// ---------------------------------------------------------------------------
// Chunked linear-recurrence scan (3 passes). Channel = threadIdx.x (coalesced).
// Composition: applying (a,b) after state s: s' = a*s + b.
// ---------------------------------------------------------------------------
template <int REV>
__global__ void scan1_kernel() {
    const int c = blockIdx.x, d = threadIdx.x;
    float Ar = 1.0f, Br = 0.0f;
    const int base = c * CH;
#pragma unroll 4
    for (int i = 0; i < CH; i++) {
        const int t = base + (REV ? (CH - 1 - i) : i);
        const float a = g_a[t * DD + d];
        const float b = g_b[t * DD + d];
        Br = fmaf(a, Br, b);
        Ar *= a;
    }
    g_Aagg[c * DD + d] = Ar;
    g_Bagg[c * DD + d] = Br;
}

template <int REV>
__global__ void scan2_kernel() {
    const int d = threadIdx.x;
    float h = 0.0f;
#pragma unroll 8
    for (int ci = 0; ci < NC; ci++) {
        const int c = REV ? (NC - 1 - ci) : ci;
        g_pref[c * DD + d] = h;
        h = fmaf(g_Aagg[c * DD + d], h, g_Bagg[c * DD + d]);
    }
}

__global__ void scan3_fwd_kernel() {
    const int c = blockIdx.x, d = threadIdx.x;
    float h = g_pref[c * DD + d];
    const int base = c * CH;
#pragma unroll 4
    for (int i = 0; i < CH; i++) {
        const int t = base + i;
        h = fmaf(g_a[t * DD + d], h, g_b[t * DD + d]);
        g_hf[t * DD + d] = h;
    }
}

// Backward scan, fused with next-layer question update: q[t] = h_bwd[t] + h_fwd[t]
__global__ void scan3_bwd_kernel() {
    const int c = blockIdx.x, d = threadIdx.x;
    float h = g_pref[c * DD + d];
    const int base = c * CH;
#pragma unroll 4
    for (int i = CH - 1; i >= 0; i--) {
        const int t = base + i;
        h = fmaf(g_a[t * DD + d], h, g_b[t * DD + d]);
        g_q[t * DD + d] = h + g_hf[t * DD + d];
    }
}

// Last layer: only h_fwd[T-1] is needed — fold chunk aggregates directly.
__global__ void final_kernel(float* __restrict__ out) {
    const int d = threadIdx.x;
    float h = 0.0f;
#pragma unroll 8
    for (int c = 0; c < NC; c++) {
        h = fmaf(g_Aagg[c * DD + d], h, g_Bagg[c * DD + d]);
    }
    out[d] = h;
}

// Broadcast question to every timestep (vectorized: one float4 per thread).
__global__ void initq_kernel(const float* __restrict__ question) {
    __shared__ float4 sq[DD / 4];
    if (threadIdx.x < DD / 4) sq[threadIdx.x] = ((const float4*)question)[threadIdx.x];
    __syncthreads();
    const long long idx = (long long)blockIdx.x * blockDim.x + threadIdx.x;  // float4 index
    ((float4*)g_q)[idx] = sq[idx & (DD / 4 - 1)];
}

// ---------------------------------------------------------------------------
extern "C" void kernel_launch(void* const* d_in, const int* in_sizes, int n_in,
                              void* d_out, int out_size) {
    const float* story = (const float*)d_in[0];
    const float* question = (const float*)d_in[1];
    const float* Wzf = (const float*)d_in[2];
    const float* bzf = (const float*)d_in[3];
    const float* Whf = (const float*)d_in[4];
    const float* bhf = (const float*)d_in[5];
    const float* Wzb = (const float*)d_in[6];
    const float* bzb = (const float*)d_in[7];
    const float* Whb = (const float*)d_in[8];
    const float* bhb = (const float*)d_in[9];
    float* out = (float*)d_out;

    const dim3 ggrid(TT / BM, DD / BN);

    // TT*DD/4 float4 stores, 256 threads/block
    initq_kernel<<<(TT * (DD / 4)) / 256, 256>>>(question);
    for (int l = 0; l < LL; l++) {
        // forward direction
        qrn_gemm<<<ggrid, 256>>>(story, Wzf + l * DD * DD, bzf + l * DD,
                                 Whf + l * 2 * DD * DD, bhf + l * DD);
        scan1_kernel<0><<<NC, DD>>>();
        if (l < LL - 1) {
            scan2_kernel<0><<<1, DD>>>();
            scan3_fwd_kernel<<<NC, DD>>>();
            // backward direction (GEMMs in forward index order; reversed scan)
            qrn_gemm<<<ggrid, 256>>>(story, Wzb + l * DD * DD, bzb + l * DD,
                                     Whb + l * 2 * DD * DD, bhb + l * DD);
            scan1_kernel<1><<<NC, DD>>>();
            scan2_kernel<1><<<1, DD>>>();
            scan3_bwd_kernel<<<NC, DD>>>();  // writes q for next layer
        } else {
            final_kernel<<<1, DD>>>(out);  // h_fwd[T-1] -> d_out
        }
    }
}

// round 6
// speedup vs baseline: 1.0028x; 1.0028x over previous
#include <cuda_runtime.h>

// ---------------------------------------------------------------------------
// QRN: 3-layer bidirectional quasi-RNN, T=65536, D=256.
// Per layer-direction:
//   z  = sigmoid((x*q) @ Wz + bz)
//   ht = tanh(x @ Wh[0:D] + q @ Wh[D:2D] + bh)
//   a = 1-z ; b = z*ht ; h_t = a_t * h_{t-1} + b_t  (scan)
// Backward direction == same GEMMs (forward order) + reversed scan.
// Output: h_fwd[T-1] of last layer (layer-2 backward pass is dead code).
// ---------------------------------------------------------------------------

#define TT 65536
#define DD 256
#define LL 3
#define BM 64
#define BN 64
#define BK 32
#define APAD 4
#define CH 256
#define NC (TT / CH)

// Scratch (device globals: no allocation allowed in kernel_launch)
__device__ float g_q[TT * DD];     // per-step question for current layer
__device__ float g_a[TT * DD];     // a = 1 - z
__device__ float g_b[TT * DD];     // b = z * h_tilde
__device__ float g_hf[TT * DD];    // forward hidden states of current layer
__device__ float g_Aagg[NC * DD];  // per-chunk scan aggregates
__device__ float g_Bagg[NC * DD];
__device__ float g_pref[NC * DD];  // per-chunk incoming prefix state

// ---- packed f32x2 helpers (FFMA2 path, sm_100+) ----
__device__ __forceinline__ unsigned long long pack2(float v) {
    unsigned long long r;
    asm("mov.b64 %0, {%1, %1};" : "=l"(r) : "f"(v));
    return r;
}
__device__ __forceinline__ unsigned long long ffma2(unsigned long long a,
                                                    unsigned long long b,
                                                    unsigned long long c) {
    unsigned long long d;
    asm("fma.rn.f32x2 %0, %1, %2, %3;" : "=l"(d) : "l"(a), "l"(b), "l"(c));
    return d;
}
__device__ __forceinline__ float2 unpack2(unsigned long long v) {
    float2 f;
    asm("mov.b64 {%0, %1}, %2;" : "=f"(f.x), "=f"(f.y) : "l"(v));
    return f;
}

__device__ __forceinline__ float fast_sigmoid(float x) {
    return 1.0f / (1.0f + __expf(-x));
}
__device__ __forceinline__ float fast_tanh(float x) {
    // 1 - 2/(e^{2x}+1): correct saturation at both ends (no inf/inf)
    return 1.0f - 2.0f / (__expf(2.0f * x) + 1.0f);
}

// ---------------------------------------------------------------------------
// Fused GEMM: computes z-preact and h-preact tiles simultaneously, applies
// sigmoid/tanh gating, writes a = 1-z and b = z*ht.
// Tile: 64x64, K-step 32, 256 threads, 4x4 outputs/thread (f32x2 along n).
// ---------------------------------------------------------------------------
__global__ __launch_bounds__(256, 2) void qrn_gemm(
    const float* __restrict__ x,
    const float* __restrict__ Wz, const float* __restrict__ bz,
    const float* __restrict__ Wh, const float* __restrict__ bh) {
    __shared__ float sX[BK][BM + APAD];
    __shared__ float sQ[BK][BM + APAD];
    __shared__ float sWz[BK][BN];
    __shared__ float sWt[BK][BN];
    __shared__ float sWb[BK][BN];

    const int tid = threadIdx.x;
    const int tx = tid & 15;   // col group (4 cols)
    const int ty = tid >> 4;   // row group (4 rows)
    const int row0 = blockIdx.x * BM;
    const int col0 = blockIdx.y * BN;
    const float* __restrict__ q = g_q;
    const float* __restrict__ Wht = Wh;            // rows 0..D-1   (x part)
    const float* __restrict__ Whb = Wh + DD * DD;  // rows D..2D-1  (q part)

    unsigned long long accz[4][2], acch[4][2];
#pragma unroll
    for (int i = 0; i < 4; i++) {
        accz[i][0] = 0ull; accz[i][1] = 0ull;
        acch[i][0] = 0ull; acch[i][1] = 0ull;
    }

    for (int k0 = 0; k0 < DD; k0 += BK) {
        // A tiles (x, q), stored transposed [k][m]
#pragma unroll
        for (int l = 0; l < 2; l++) {
            int s = tid + l * 256;
            int m = s >> 3;
            int kk = (s & 7) << 2;
            const float4 vx = *(const float4*)&x[(row0 + m) * DD + k0 + kk];
            const float4 vq = *(const float4*)&q[(row0 + m) * DD + k0 + kk];
            sX[kk + 0][m] = vx.x; sX[kk + 1][m] = vx.y;
            sX[kk + 2][m] = vx.z; sX[kk + 3][m] = vx.w;
            sQ[kk + 0][m] = vq.x; sQ[kk + 1][m] = vq.y;
            sQ[kk + 2][m] = vq.z; sQ[kk + 3][m] = vq.w;
        }
        // B tiles (Wz, Wh_top, Wh_bot), natural [k][n]
#pragma unroll
        for (int l = 0; l < 2; l++) {
            int s = tid + l * 256;
            int k = s >> 4;
            int n4 = (s & 15) << 2;
            *(float4*)&sWz[k][n4] = *(const float4*)&Wz[(k0 + k) * DD + col0 + n4];
            *(float4*)&sWt[k][n4] = *(const float4*)&Wht[(k0 + k) * DD + col0 + n4];
            *(float4*)&sWb[k][n4] = *(const float4*)&Whb[(k0 + k) * DD + col0 + n4];
        }
        __syncthreads();
#pragma unroll
        for (int k = 0; k < BK; k++) {
            float4 xf = *(const float4*)&sX[k][ty << 2];
            float4 qf = *(const float4*)&sQ[k][ty << 2];
            ulonglong2 wz = *(const ulonglong2*)&sWz[k][tx << 2];
            ulonglong2 wt = *(const ulonglong2*)&sWt[k][tx << 2];
            ulonglong2 wb = *(const ulonglong2*)&sWb[k][tx << 2];
            const float xs[4] = {xf.x, xf.y, xf.z, xf.w};
            const float qs[4] = {qf.x, qf.y, qf.z, qf.w};
#pragma unroll
            for (int i = 0; i < 4; i++) {
                unsigned long long X2 = pack2(xs[i]);
                unsigned long long Q2 = pack2(qs[i]);
                unsigned long long XQ2 = pack2(xs[i] * qs[i]);
                accz[i][0] = ffma2(XQ2, wz.x, accz[i][0]);
                accz[i][1] = ffma2(XQ2, wz.y, accz[i][1]);
                acch[i][0] = ffma2(X2, wt.x, acch[i][0]);
                acch[i][1] = ffma2(X2, wt.y, acch[i][1]);
                acch[i][0] = ffma2(Q2, wb.x, acch[i][0]);
                acch[i][1] = ffma2(Q2, wb.y, acch[i][1]);
            }
        }
        __syncthreads();
    }

    // Epilogue: gate + write a, b
    const float4 bz4 = *(const float4*)&bz[col0 + (tx << 2)];
    const float4 bh4 = *(const float4*)&bh[col0 + (tx << 2)];
#pragma unroll
    for (int i = 0; i < 4; i++) {
        float2 z01 = unpack2(accz[i][0]);
        float2 z23 = unpack2(accz[i][1]);
        float2 h01 = unpack2(acch[i][0]);
        float2 h23 = unpack2(acch[i][1]);
        float zp[4] = {z01.x + bz4.x, z01.y + bz4.y, z23.x + bz4.z, z23.y + bz4.w};
        float hp[4] = {h01.x + bh4.x, h01.y + bh4.y, h23.x + bh4.z, h23.y + bh4.w};
        float4 av, bv;
        float* avp = &av.x;
        float* bvp = &bv.x;
#pragma unroll
        for (int j = 0; j < 4; j++) {
            float z = fast_sigmoid(zp[j]);
            float ht = fast_tanh(hp[j]);
            avp[j] = 1.0f - z;
            bvp[j] = z * ht;
        }
        const int gm = row0 + (ty << 2) + i;
        *(float4*)&g_a[gm * DD + col0 + (tx << 2)] = av;
        *(float4*)&g_b[gm * DD + col0 + (tx << 2)] = bv;
    }
}

// ---------------------------------------------------------------------------
// Chunked linear-recurrence scan (3 passes). Channel = threadIdx.x (coalesced).
// Composition: applying (a,b) after state s: s' = a*s + b.
// ---------------------------------------------------------------------------
template <int REV>
__global__ void scan1_kernel() {
    const int c = blockIdx.x, d = threadIdx.x;
    float Ar = 1.0f, Br = 0.0f;
    const int base = c * CH;
#pragma unroll 4
    for (int i = 0; i < CH; i++) {
        const int t = base + (REV ? (CH - 1 - i) : i);
        const float a = g_a[t * DD + d];
        const float b = g_b[t * DD + d];
        Br = fmaf(a, Br, b);
        Ar *= a;
    }
    g_Aagg[c * DD + d] = Ar;
    g_Bagg[c * DD + d] = Br;
}

template <int REV>
__global__ void scan2_kernel() {
    const int d = threadIdx.x;
    float h = 0.0f;
#pragma unroll 8
    for (int ci = 0; ci < NC; ci++) {
        const int c = REV ? (NC - 1 - ci) : ci;
        g_pref[c * DD + d] = h;
        h = fmaf(g_Aagg[c * DD + d], h, g_Bagg[c * DD + d]);
    }
}

__global__ void scan3_fwd_kernel() {
    const int c = blockIdx.x, d = threadIdx.x;
    float h = g_pref[c * DD + d];
    const int base = c * CH;
#pragma unroll 4
    for (int i = 0; i < CH; i++) {
        const int t = base + i;
        h = fmaf(g_a[t * DD + d], h, g_b[t * DD + d]);
        g_hf[t * DD + d] = h;
    }
}

// Backward scan, fused with next-layer question update: q[t] = h_bwd[t] + h_fwd[t]
__global__ void scan3_bwd_kernel() {
    const int c = blockIdx.x, d = threadIdx.x;
    float h = g_pref[c * DD + d];
    const int base = c * CH;
#pragma unroll 4
    for (int i = CH - 1; i >= 0; i--) {
        const int t = base + i;
        h = fmaf(g_a[t * DD + d], h, g_b[t * DD + d]);
        g_q[t * DD + d] = h + g_hf[t * DD + d];
    }
}

// Last layer: only h_fwd[T-1] is needed — fold chunk aggregates directly.
__global__ void final_kernel(float* __restrict__ out) {
    const int d = threadIdx.x;
    float h = 0.0f;
#pragma unroll 8
    for (int c = 0; c < NC; c++) {
        h = fmaf(g_Aagg[c * DD + d], h, g_Bagg[c * DD + d]);
    }
    out[d] = h;
}

// Broadcast question to every timestep (vectorized: one float4 per thread).
__global__ void initq_kernel(const float* __restrict__ question) {
    __shared__ float4 sq[DD / 4];
    if (threadIdx.x < DD / 4) sq[threadIdx.x] = ((const float4*)question)[threadIdx.x];
    __syncthreads();
    const long long idx = (long long)blockIdx.x * blockDim.x + threadIdx.x;  // float4 index
    ((float4*)g_q)[idx] = sq[idx & (DD / 4 - 1)];
}

// ---------------------------------------------------------------------------
extern "C" void kernel_launch(void* const* d_in, const int* in_sizes, int n_in,
                              void* d_out, int out_size) {
    const float* story = (const float*)d_in[0];
    const float* question = (const float*)d_in[1];
    const float* Wzf = (const float*)d_in[2];
    const float* bzf = (const float*)d_in[3];
    const float* Whf = (const float*)d_in[4];
    const float* bhf = (const float*)d_in[5];
    const float* Wzb = (const float*)d_in[6];
    const float* bzb = (const float*)d_in[7];
    const float* Whb = (const float*)d_in[8];
    const float* bhb = (const float*)d_in[9];
    float* out = (float*)d_out;

    const dim3 ggrid(TT / BM, DD / BN);

    // TT*DD/4 float4 stores, 256 threads/block
    initq_kernel<<<(TT * (DD / 4)) / 256, 256>>>(question);
    for (int l = 0; l < LL; l++) {
        // forward direction
        qrn_gemm<<<ggrid, 256>>>(story, Wzf + l * DD * DD, bzf + l * DD,
                                 Whf + l * 2 * DD * DD, bhf + l * DD);
        scan1_kernel<0><<<NC, DD>>>();
        if (l < LL - 1) {
            scan2_kernel<0><<<1, DD>>>();
            scan3_fwd_kernel<<<NC, DD>>>();
            // backward direction (GEMMs in forward index order; reversed scan)
            qrn_gemm<<<ggrid, 256>>>(story, Wzb + l * DD * DD, bzb + l * DD,
                                     Whb + l * 2 * DD * DD, bhb + l * DD);
            scan1_kernel<1><<<NC, DD>>>();
            scan2_kernel<1><<<1, DD>>>();
            scan3_bwd_kernel<<<NC, DD>>>();  // writes q for next layer
        } else {
            final_kernel<<<1, DD>>>(out);  // h_fwd[T-1] -> d_out
        }
    }
}

// round 7
// speedup vs baseline: 1.1791x; 1.1759x over previous
#include <cuda_runtime.h>

// ---------------------------------------------------------------------------
// QRN: 3-layer bidirectional quasi-RNN, T=65536, D=256.
// Per layer-direction:
//   z  = sigmoid((x*q) @ Wz + bz)
//   ht = tanh(x @ Wh[0:D] + q @ Wh[D:2D] + bh)
//   a = 1-z ; b = z*ht ; h_t = a_t * h_{t-1} + b_t  (scan)
// Backward direction == same GEMMs (forward order) + reversed scan.
// Output: h_fwd[T-1] of last layer (layer-2 backward pass is dead code).
//
// Layer-0 special case: q is the constant question vector, so
//   (x*q)@Wz == x @ (diag(q)·Wz)   and   q@Wh_bot + bh == const vector.
// We fold both on-device and run a leaner layer-0 GEMM (no q operand at all).
// ---------------------------------------------------------------------------

#define TT 65536
#define DD 256
#define LL 3
#define BM 64
#define BN 64
#define BK 32
#define APAD 4
#define CH 256
#define NC (TT / CH)

// Scratch (device globals: no allocation allowed in kernel_launch)
__device__ float g_q[TT * DD];     // per-step question for layers >= 1
__device__ float g_a[TT * DD];     // a = 1 - z
__device__ float g_b[TT * DD];     // b = z * h_tilde
__device__ float g_hf[TT * DD];    // forward hidden states of current layer
__device__ float g_Aagg[NC * DD];  // per-chunk scan aggregates
__device__ float g_Bagg[NC * DD];
__device__ float g_pref[NC * DD];  // per-chunk incoming prefix state
__device__ float g_Wz0f[DD * DD];  // layer-0 folded weights / consts
__device__ float g_ch0f[DD];
__device__ float g_Wz0b[DD * DD];
__device__ float g_ch0b[DD];

// ---- packed f32x2 helpers (FFMA2 path, sm_100+) ----
__device__ __forceinline__ unsigned long long pack2(float v) {
    unsigned long long r;
    asm("mov.b64 %0, {%1, %1};" : "=l"(r) : "f"(v));
    return r;
}
__device__ __forceinline__ unsigned long long ffma2(unsigned long long a,
                                                    unsigned long long b,
                                                    unsigned long long c) {
    unsigned long long d;
    asm("fma.rn.f32x2 %0, %1, %2, %3;" : "=l"(d) : "l"(a), "l"(b), "l"(c));
    return d;
}
__device__ __forceinline__ float2 unpack2(unsigned long long v) {
    float2 f;
    asm("mov.b64 {%0, %1}, %2;" : "=f"(f.x), "=f"(f.y) : "l"(v));
    return f;
}

__device__ __forceinline__ float fast_sigmoid(float x) {
    return 1.0f / (1.0f + __expf(-x));
}
__device__ __forceinline__ float fast_tanh(float x) {
    // 1 - 2/(e^{2x}+1): correct saturation at both ends (no inf/inf)
    return 1.0f - 2.0f / (__expf(2.0f * x) + 1.0f);
}

// ---------------------------------------------------------------------------
// Layer-0 folding: Wz' = diag(q) * Wz ;  ch = q @ Wh_bot + bh
// ---------------------------------------------------------------------------
__global__ void fold_wz_kernel(const float* __restrict__ question,
                               const float* __restrict__ Wz,
                               float* __restrict__ Wzp) {
    const int k = blockIdx.x, n = threadIdx.x;
    Wzp[k * DD + n] = question[k] * Wz[k * DD + n];
}

__global__ void fold_ch_kernel(const float* __restrict__ question,
                               const float* __restrict__ Whbot,
                               const float* __restrict__ bh,
                               float* __restrict__ ch) {
    const int n = threadIdx.x;
    float s = bh[n];
    for (int k = 0; k < DD; k++) s = fmaf(question[k], Whbot[k * DD + n], s);
    ch[n] = s;
}

// ---------------------------------------------------------------------------
// Fused GEMM (layers >= 1): z-preact and h-preact tiles simultaneously, then
// gate and write a = 1-z, b = z*ht. 64x64 tile, BK=32, 256 thr, 4x4 outputs.
// ---------------------------------------------------------------------------
__global__ __launch_bounds__(256, 2) void qrn_gemm(
    const float* __restrict__ x,
    const float* __restrict__ Wz, const float* __restrict__ bz,
    const float* __restrict__ Wh, const float* __restrict__ bh) {
    __shared__ float sX[BK][BM + APAD];
    __shared__ float sQ[BK][BM + APAD];
    __shared__ float sWz[BK][BN];
    __shared__ float sWt[BK][BN];
    __shared__ float sWb[BK][BN];

    const int tid = threadIdx.x;
    const int tx = tid & 15;   // col group (4 cols)
    const int ty = tid >> 4;   // row group (4 rows)
    const int row0 = blockIdx.x * BM;
    const int col0 = blockIdx.y * BN;
    const float* __restrict__ q = g_q;
    const float* __restrict__ Wht = Wh;            // rows 0..D-1   (x part)
    const float* __restrict__ Whb = Wh + DD * DD;  // rows D..2D-1  (q part)

    unsigned long long accz[4][2], acch[4][2];
#pragma unroll
    for (int i = 0; i < 4; i++) {
        accz[i][0] = 0ull; accz[i][1] = 0ull;
        acch[i][0] = 0ull; acch[i][1] = 0ull;
    }

    for (int k0 = 0; k0 < DD; k0 += BK) {
#pragma unroll
        for (int l = 0; l < 2; l++) {
            int s = tid + l * 256;
            int m = s >> 3;
            int kk = (s & 7) << 2;
            const float4 vx = *(const float4*)&x[(row0 + m) * DD + k0 + kk];
            const float4 vq = *(const float4*)&q[(row0 + m) * DD + k0 + kk];
            sX[kk + 0][m] = vx.x; sX[kk + 1][m] = vx.y;
            sX[kk + 2][m] = vx.z; sX[kk + 3][m] = vx.w;
            sQ[kk + 0][m] = vq.x; sQ[kk + 1][m] = vq.y;
            sQ[kk + 2][m] = vq.z; sQ[kk + 3][m] = vq.w;
        }
#pragma unroll
        for (int l = 0; l < 2; l++) {
            int s = tid + l * 256;
            int k = s >> 4;
            int n4 = (s & 15) << 2;
            *(float4*)&sWz[k][n4] = *(const float4*)&Wz[(k0 + k) * DD + col0 + n4];
            *(float4*)&sWt[k][n4] = *(const float4*)&Wht[(k0 + k) * DD + col0 + n4];
            *(float4*)&sWb[k][n4] = *(const float4*)&Whb[(k0 + k) * DD + col0 + n4];
        }
        __syncthreads();
#pragma unroll
        for (int k = 0; k < BK; k++) {
            float4 xf = *(const float4*)&sX[k][ty << 2];
            float4 qf = *(const float4*)&sQ[k][ty << 2];
            ulonglong2 wz = *(const ulonglong2*)&sWz[k][tx << 2];
            ulonglong2 wt = *(const ulonglong2*)&sWt[k][tx << 2];
            ulonglong2 wb = *(const ulonglong2*)&sWb[k][tx << 2];
            const float xs[4] = {xf.x, xf.y, xf.z, xf.w};
            const float qs[4] = {qf.x, qf.y, qf.z, qf.w};
#pragma unroll
            for (int i = 0; i < 4; i++) {
                unsigned long long X2 = pack2(xs[i]);
                unsigned long long Q2 = pack2(qs[i]);
                unsigned long long XQ2 = pack2(xs[i] * qs[i]);
                accz[i][0] = ffma2(XQ2, wz.x, accz[i][0]);
                accz[i][1] = ffma2(XQ2, wz.y, accz[i][1]);
                acch[i][0] = ffma2(X2, wt.x, acch[i][0]);
                acch[i][1] = ffma2(X2, wt.y, acch[i][1]);
                acch[i][0] = ffma2(Q2, wb.x, acch[i][0]);
                acch[i][1] = ffma2(Q2, wb.y, acch[i][1]);
            }
        }
        __syncthreads();
    }

    const float4 bz4 = *(const float4*)&bz[col0 + (tx << 2)];
    const float4 bh4 = *(const float4*)&bh[col0 + (tx << 2)];
#pragma unroll
    for (int i = 0; i < 4; i++) {
        float2 z01 = unpack2(accz[i][0]);
        float2 z23 = unpack2(accz[i][1]);
        float2 h01 = unpack2(acch[i][0]);
        float2 h23 = unpack2(acch[i][1]);
        float zp[4] = {z01.x + bz4.x, z01.y + bz4.y, z23.x + bz4.z, z23.y + bz4.w};
        float hp[4] = {h01.x + bh4.x, h01.y + bh4.y, h23.x + bh4.z, h23.y + bh4.w};
        float4 av, bv;
        float* avp = &av.x;
        float* bvp = &bv.x;
#pragma unroll
        for (int j = 0; j < 4; j++) {
            float z = fast_sigmoid(zp[j]);
            float ht = fast_tanh(hp[j]);
            avp[j] = 1.0f - z;
            bvp[j] = z * ht;
        }
        const int gm = row0 + (ty << 2) + i;
        *(float4*)&g_a[gm * DD + col0 + (tx << 2)] = av;
        *(float4*)&g_b[gm * DD + col0 + (tx << 2)] = bv;
    }
}

// ---------------------------------------------------------------------------
// Layer-0 GEMM: q folded into weights. z = x@Wz' + bz ; h = x@Wht + ch.
// 2/3 of the FMAs, 3/5 of the smem traffic of the general kernel.
// ---------------------------------------------------------------------------
__global__ __launch_bounds__(256, 2) void qrn_gemm_l0(
    const float* __restrict__ x,
    const float* __restrict__ Wzp, const float* __restrict__ bz,
    const float* __restrict__ Wht, const float* __restrict__ ch) {
    __shared__ float sX[BK][BM + APAD];
    __shared__ float sWz[BK][BN];
    __shared__ float sWt[BK][BN];

    const int tid = threadIdx.x;
    const int tx = tid & 15;
    const int ty = tid >> 4;
    const int row0 = blockIdx.x * BM;
    const int col0 = blockIdx.y * BN;

    unsigned long long accz[4][2], acch[4][2];
#pragma unroll
    for (int i = 0; i < 4; i++) {
        accz[i][0] = 0ull; accz[i][1] = 0ull;
        acch[i][0] = 0ull; acch[i][1] = 0ull;
    }

    for (int k0 = 0; k0 < DD; k0 += BK) {
#pragma unroll
        for (int l = 0; l < 2; l++) {
            int s = tid + l * 256;
            int m = s >> 3;
            int kk = (s & 7) << 2;
            const float4 vx = *(const float4*)&x[(row0 + m) * DD + k0 + kk];
            sX[kk + 0][m] = vx.x; sX[kk + 1][m] = vx.y;
            sX[kk + 2][m] = vx.z; sX[kk + 3][m] = vx.w;
        }
#pragma unroll
        for (int l = 0; l < 2; l++) {
            int s = tid + l * 256;
            int k = s >> 4;
            int n4 = (s & 15) << 2;
            *(float4*)&sWz[k][n4] = *(const float4*)&Wzp[(k0 + k) * DD + col0 + n4];
            *(float4*)&sWt[k][n4] = *(const float4*)&Wht[(k0 + k) * DD + col0 + n4];
        }
        __syncthreads();
#pragma unroll
        for (int k = 0; k < BK; k++) {
            float4 xf = *(const float4*)&sX[k][ty << 2];
            ulonglong2 wz = *(const ulonglong2*)&sWz[k][tx << 2];
            ulonglong2 wt = *(const ulonglong2*)&sWt[k][tx << 2];
            const float xs[4] = {xf.x, xf.y, xf.z, xf.w};
#pragma unroll
            for (int i = 0; i < 4; i++) {
                unsigned long long X2 = pack2(xs[i]);
                accz[i][0] = ffma2(X2, wz.x, accz[i][0]);
                accz[i][1] = ffma2(X2, wz.y, accz[i][1]);
                acch[i][0] = ffma2(X2, wt.x, acch[i][0]);
                acch[i][1] = ffma2(X2, wt.y, acch[i][1]);
            }
        }
        __syncthreads();
    }

    const float4 bz4 = *(const float4*)&bz[col0 + (tx << 2)];
    const float4 ch4 = *(const float4*)&ch[col0 + (tx << 2)];  // includes bh
#pragma unroll
    for (int i = 0; i < 4; i++) {
        float2 z01 = unpack2(accz[i][0]);
        float2 z23 = unpack2(accz[i][1]);
        float2 h01 = unpack2(acch[i][0]);
        float2 h23 = unpack2(acch[i][1]);
        float zp[4] = {z01.x + bz4.x, z01.y + bz4.y, z23.x + bz4.z, z23.y + bz4.w};
        float hp[4] = {h01.x + ch4.x, h01.y + ch4.y, h23.x + ch4.z, h23.y + ch4.w};
        float4 av, bv;
        float* avp = &av.x;
        float* bvp = &bv.x;
#pragma unroll
        for (int j = 0; j < 4; j++) {
            float z = fast_sigmoid(zp[j]);
            float ht = fast_tanh(hp[j]);
            avp[j] = 1.0f - z;
            bvp[j] = z * ht;
        }
        const int gm = row0 + (ty << 2) + i;
        *(float4*)&g_a[gm * DD + col0 + (tx << 2)] = av;
        *(float4*)&g_b[gm * DD + col0 + (tx << 2)] = bv;
    }
}

// ---------------------------------------------------------------------------
// Chunked linear-recurrence scan (3 passes). Channel = threadIdx.x (coalesced).
// ---------------------------------------------------------------------------
template <int REV>
__global__ void scan1_kernel() {
    const int c = blockIdx.x, d = threadIdx.x;
    float Ar = 1.0f, Br = 0.0f;
    const int base = c * CH;
#pragma unroll 4
    for (int i = 0; i < CH; i++) {
        const int t = base + (REV ? (CH - 1 - i) : i);
        const float a = g_a[t * DD + d];
        const float b = g_b[t * DD + d];
        Br = fmaf(a, Br, b);
        Ar *= a;
    }
    g_Aagg[c * DD + d] = Ar;
    g_Bagg[c * DD + d] = Br;
}

// Cross-chunk prefix scan. 8 blocks x 32 threads (one thread per channel),
// batch-prefetch 16 aggregate pairs so the LDG latency pipelines ahead of
// the dependent-FMA chain (was: grid=1 latency chain, 139us).
#define S2_BATCH 16
template <int REV>
__global__ void scan2_kernel() {
    const int d = blockIdx.x * 32 + threadIdx.x;
    float h = 0.0f;
    for (int ci0 = 0; ci0 < NC; ci0 += S2_BATCH) {
        float A[S2_BATCH], B[S2_BATCH];
#pragma unroll
        for (int j = 0; j < S2_BATCH; j++) {
            const int c = REV ? (NC - 1 - (ci0 + j)) : (ci0 + j);
            A[j] = g_Aagg[c * DD + d];
            B[j] = g_Bagg[c * DD + d];
        }
#pragma unroll
        for (int j = 0; j < S2_BATCH; j++) {
            const int c = REV ? (NC - 1 - (ci0 + j)) : (ci0 + j);
            g_pref[c * DD + d] = h;
            h = fmaf(A[j], h, B[j]);
        }
    }
}

__global__ void scan3_fwd_kernel() {
    const int c = blockIdx.x, d = threadIdx.x;
    float h = g_pref[c * DD + d];
    const int base = c * CH;
#pragma unroll 4
    for (int i = 0; i < CH; i++) {
        const int t = base + i;
        h = fmaf(g_a[t * DD + d], h, g_b[t * DD + d]);
        g_hf[t * DD + d] = h;
    }
}

// Backward scan, fused with next-layer question: q[t] = h_bwd[t] + h_fwd[t]
__global__ void scan3_bwd_kernel() {
    const int c = blockIdx.x, d = threadIdx.x;
    float h = g_pref[c * DD + d];
    const int base = c * CH;
#pragma unroll 4
    for (int i = CH - 1; i >= 0; i--) {
        const int t = base + i;
        h = fmaf(g_a[t * DD + d], h, g_b[t * DD + d]);
        g_q[t * DD + d] = h + g_hf[t * DD + d];
    }
}

// Last layer: fold chunk aggregates straight into h_fwd[T-1]. Same
// batch-prefetch treatment as scan2.
__global__ void final_kernel(float* __restrict__ out) {
    const int d = blockIdx.x * 32 + threadIdx.x;
    float h = 0.0f;
    for (int c0 = 0; c0 < NC; c0 += S2_BATCH) {
        float A[S2_BATCH], B[S2_BATCH];
#pragma unroll
        for (int j = 0; j < S2_BATCH; j++) {
            A[j] = g_Aagg[(c0 + j) * DD + d];
            B[j] = g_Bagg[(c0 + j) * DD + d];
        }
#pragma unroll
        for (int j = 0; j < S2_BATCH; j++) h = fmaf(A[j], h, B[j]);
    }
    out[d] = h;
}

// ---------------------------------------------------------------------------
extern "C" void kernel_launch(void* const* d_in, const int* in_sizes, int n_in,
                              void* d_out, int out_size) {
    const float* story = (const float*)d_in[0];
    const float* question = (const float*)d_in[1];
    const float* Wzf = (const float*)d_in[2];
    const float* bzf = (const float*)d_in[3];
    const float* Whf = (const float*)d_in[4];
    const float* bhf = (const float*)d_in[5];
    const float* Wzb = (const float*)d_in[6];
    const float* bzb = (const float*)d_in[7];
    const float* Whb = (const float*)d_in[8];
    const float* bhb = (const float*)d_in[9];
    float* out = (float*)d_out;

    const dim3 ggrid(TT / BM, DD / BN);
    float* Wz0f;  cudaGetSymbolAddress((void**)&Wz0f, g_Wz0f);
    float* ch0f;  cudaGetSymbolAddress((void**)&ch0f, g_ch0f);
    float* Wz0b;  cudaGetSymbolAddress((void**)&Wz0b, g_Wz0b);
    float* ch0b;  cudaGetSymbolAddress((void**)&ch0b, g_ch0b);

    // Layer-0 folding (q constant): Wz' = diag(q)Wz ; ch = q@Wh_bot + bh
    fold_wz_kernel<<<DD, DD>>>(question, Wzf, Wz0f);
    fold_ch_kernel<<<1, DD>>>(question, Whf + DD * DD, bhf, ch0f);
    fold_wz_kernel<<<DD, DD>>>(question, Wzb, Wz0b);
    fold_ch_kernel<<<1, DD>>>(question, Whb + DD * DD, bhb, ch0b);

    // ---- layer 0 (folded) ----
    qrn_gemm_l0<<<ggrid, 256>>>(story, Wz0f, bzf, Whf, ch0f);
    scan1_kernel<0><<<NC, DD>>>();
    scan2_kernel<0><<<8, 32>>>();
    scan3_fwd_kernel<<<NC, DD>>>();
    qrn_gemm_l0<<<ggrid, 256>>>(story, Wz0b, bzb, Whb, ch0b);
    scan1_kernel<1><<<NC, DD>>>();
    scan2_kernel<1><<<8, 32>>>();
    scan3_bwd_kernel<<<NC, DD>>>();  // writes q for layer 1

    // ---- layers 1..2 ----
    for (int l = 1; l < LL; l++) {
        qrn_gemm<<<ggrid, 256>>>(story, Wzf + l * DD * DD, bzf + l * DD,
                                 Whf + l * 2 * DD * DD, bhf + l * DD);
        scan1_kernel<0><<<NC, DD>>>();
        if (l < LL - 1) {
            scan2_kernel<0><<<8, 32>>>();
            scan3_fwd_kernel<<<NC, DD>>>();
            qrn_gemm<<<ggrid, 256>>>(story, Wzb + l * DD * DD, bzb + l * DD,
                                     Whb + l * 2 * DD * DD, bhb + l * DD);
            scan1_kernel<1><<<NC, DD>>>();
            scan2_kernel<1><<<8, 32>>>();
            scan3_bwd_kernel<<<NC, DD>>>();
        } else {
            final_kernel<<<8, 32>>>(out);  // h_fwd[T-1] -> d_out
        }
    }
}

// round 10
// speedup vs baseline: 1.5990x; 1.3561x over previous
#include <cuda_runtime.h>
#include <cuda_bf16.h>
#include <cstdint>

// ---------------------------------------------------------------------------
// QRN: 3-layer bidirectional quasi-RNN, T=65536, D=256.
// mma.sync (HMMA bf16, fp32 accum) version — tcgen05 is unavailable because
// the harness PTX target is plain sm_103 (no 'a' feature, verified R9).
// Per layer-direction:
//   z  = sigmoid((x*q) @ Wz + bz)
//   ht = tanh(x @ Wh[0:D] + q @ Wh[D:2D] + bh)
//   a = 1-z ; b = z*ht ; h_t = a_t*h_{t-1} + b_t  (scan)
// 3-term bf16 split (hi*hi + hi*lo + lo*hi) recovers fp32-grade accuracy.
// Layer-0: q constant -> fold diag(q)Wz and q@Wh_bot+bh (A-operand = x only).
// Output: h_fwd[T-1] of last layer (layer-2 backward pass is dead code).
// ---------------------------------------------------------------------------

#define TT 65536
#define DD 256
#define CH 256
#define NC (TT / CH)

typedef __nv_bfloat16 bf16;

// ----- scratch (device globals; no runtime allocation allowed) -----
__device__ float g_a[TT * DD];
__device__ float g_b[TT * DD];
__device__ float g_hf[TT * DD];
__device__ float g_zpre[TT * DD];
__device__ float g_hpre[TT * DD];
__device__ float g_Aagg[NC * DD];
__device__ float g_Bagg[NC * DD];
__device__ float g_pref[NC * DD];
__device__ float g_Wz0f[DD * DD];
__device__ float g_ch0f[DD];
__device__ float g_Wz0b[DD * DD];
__device__ float g_ch0b[DD];

// bf16 split operands
__device__ bf16 g_xcat_h[TT * 512];  // [t][0:256]=x, [256:512]=q (per layer)
__device__ bf16 g_xcat_l[TT * 512];
__device__ bf16 g_xq_h[TT * DD];     // x*q (layers >= 1)
__device__ bf16 g_xq_l[TT * DD];

// transposed K-major bf16 weights: [n][k]
__device__ bf16 g_Wz0fT_h[DD * DD], g_Wz0fT_l[DD * DD];
__device__ bf16 g_Wz0bT_h[DD * DD], g_Wz0bT_l[DD * DD];
__device__ bf16 g_Wt0fT_h[DD * DD], g_Wt0fT_l[DD * DD];   // layer-0 Wh top
__device__ bf16 g_Wt0bT_h[DD * DD], g_Wt0bT_l[DD * DD];
__device__ bf16 g_WzT_h[3 * DD * DD], g_WzT_l[3 * DD * DD];      // f1,f2,b1
__device__ bf16 g_WhT_h[3 * DD * 512], g_WhT_l[3 * DD * 512];    // f1,f2,b1

__device__ __forceinline__ float fast_sigmoid(float x) {
    return 1.0f / (1.0f + __expf(-x));
}
__device__ __forceinline__ float fast_tanh(float x) {
    return 1.0f - 2.0f / (__expf(2.0f * x) + 1.0f);
}

__device__ __forceinline__ uint32_t smem_u32(const void* p) {
    uint32_t a;
    asm("{ .reg .u64 t; cvta.to.shared.u64 t, %1; cvt.u32.u64 %0, t; }"
        : "=r"(a) : "l"(p));
    return a;
}
__device__ __forceinline__ void ldmx4(uint32_t* r, uint32_t addr) {
    asm volatile(
        "ldmatrix.sync.aligned.m8n8.x4.shared.b16 {%0,%1,%2,%3}, [%4];"
        : "=r"(r[0]), "=r"(r[1]), "=r"(r[2]), "=r"(r[3]) : "r"(addr));
}
__device__ __forceinline__ void mma_bf16(float* c, const uint32_t* a,
                                         const uint32_t* b) {
    asm volatile(
        "mma.sync.aligned.m16n8k16.row.col.f32.bf16.bf16.f32 "
        "{%0,%1,%2,%3}, {%4,%5,%6,%7}, {%8,%9}, {%0,%1,%2,%3};"
        : "+f"(c[0]), "+f"(c[1]), "+f"(c[2]), "+f"(c[3])
        : "r"(a[0]), "r"(a[1]), "r"(a[2]), "r"(a[3]), "r"(b[0]), "r"(b[1]));
}

// ---------------------------------------------------------------------------
// bf16-split GEMM: C[M,256] = A[M,K] @ B[256,K]^T, 3-term hi/lo.
// CTA tile 128x128 (grid.y = 2 covers N=256), BK=32, 8 warps of 32x64.
// smem: padded stride 56 bf16 (112B): 16B-aligned rows, conflict-free ldmatrix.
// ---------------------------------------------------------------------------
#define GSTR 56
#define SM_AH 0
#define SM_AL (128 * GSTR)
#define SM_BH (2 * 128 * GSTR)
#define SM_BL (3 * 128 * GSTR)
#define GEMM_SMEM (4 * 128 * GSTR * 2)  // bytes = 57344

__global__ __launch_bounds__(256) void qrn_gemm_mma(
    const bf16* __restrict__ Ah, const bf16* __restrict__ Al, int lda, int K,
    const bf16* __restrict__ Bh, const bf16* __restrict__ Bl,
    float* __restrict__ Cout) {
    extern __shared__ bf16 sm[];
    const uint32_t sbase = smem_u32(sm);
    const int tid = threadIdx.x;
    const int wid = tid >> 5;
    const int lane = tid & 31;
    const int m0 = blockIdx.x * 128;
    const int n0 = blockIdx.y * 128;
    const int wm = (wid & 3) * 32;   // warp m-offset within tile
    const int wn = (wid >> 2) * 64;  // warp n-offset

    float c[2][8][4];
#pragma unroll
    for (int mt = 0; mt < 2; mt++)
#pragma unroll
        for (int nt = 0; nt < 8; nt++)
#pragma unroll
            for (int j = 0; j < 4; j++) c[mt][nt][j] = 0.0f;

    // ldmatrix source addresses (fixed per thread per kstep-parity)
    // A x4: i/8==0:(m+i%8, k) 1:(m+8+i%8, k) 2:(m+i%8, k+8) 3:(m+8+i%8, k+8)
    const int la_row = (lane & 7) + ((lane >> 3) & 1) * 8;  // + wm + mt*16
    const int la_k = (lane >> 4) * 8;
    // B x4 (two n8 tiles): 0:(n+i%8,k) 1:(n+i%8,k+8) 2:(n+8+i%8,k) 3:(n+8+i%8,k+8)
    const int lb_row = (lane & 7) + (lane >> 4) * 8;  // + wn + ntp*16
    const int lb_k = ((lane >> 3) & 1) * 8;

    for (int k0 = 0; k0 < K; k0 += 32) {
        __syncthreads();
        // load A/B chunks [128][32] hi+lo into padded smem
#pragma unroll
        for (int l = 0; l < 2; l++) {
            const int i = tid + l * 256;       // uint4 index, 512 per array
            const int r = i >> 2, c16 = i & 3; // 4 uint4 per row
            const uint32_t so = (r * GSTR + c16 * 8) * 2;
            *(uint4*)((char*)sm + SM_AH * 2 + so) =
                *(const uint4*)(Ah + (size_t)(m0 + r) * lda + k0 + c16 * 8);
            *(uint4*)((char*)sm + SM_AL * 2 + so) =
                *(const uint4*)(Al + (size_t)(m0 + r) * lda + k0 + c16 * 8);
            *(uint4*)((char*)sm + SM_BH * 2 + so) =
                *(const uint4*)(Bh + (size_t)(n0 + r) * K + k0 + c16 * 8);
            *(uint4*)((char*)sm + SM_BL * 2 + so) =
                *(const uint4*)(Bl + (size_t)(n0 + r) * K + k0 + c16 * 8);
        }
        __syncthreads();

#pragma unroll
        for (int ks = 0; ks < 32; ks += 16) {
            uint32_t ah[2][4], al[2][4], bh[8][2], bl[8][2];
#pragma unroll
            for (int mt = 0; mt < 2; mt++) {
                const uint32_t ra =
                    sbase + ((wm + mt * 16 + la_row) * GSTR + ks + la_k) * 2;
                ldmx4(ah[mt], ra + SM_AH * 2);
                ldmx4(al[mt], ra + SM_AL * 2);
            }
#pragma unroll
            for (int ntp = 0; ntp < 4; ntp++) {
                const uint32_t rb =
                    sbase + ((wn + ntp * 16 + lb_row) * GSTR + ks + lb_k) * 2;
                uint32_t t[4];
                ldmx4(t, rb + SM_BH * 2);
                bh[ntp * 2][0] = t[0]; bh[ntp * 2][1] = t[1];
                bh[ntp * 2 + 1][0] = t[2]; bh[ntp * 2 + 1][1] = t[3];
                ldmx4(t, rb + SM_BL * 2);
                bl[ntp * 2][0] = t[0]; bl[ntp * 2][1] = t[1];
                bl[ntp * 2 + 1][0] = t[2]; bl[ntp * 2 + 1][1] = t[3];
            }
#pragma unroll
            for (int mt = 0; mt < 2; mt++)
#pragma unroll
                for (int nt = 0; nt < 8; nt++) {
                    mma_bf16(c[mt][nt], ah[mt], bh[nt]);
                    mma_bf16(c[mt][nt], al[mt], bh[nt]);
                    mma_bf16(c[mt][nt], ah[mt], bl[nt]);
                }
        }
    }

    // epilogue: write fp32 preacts
#pragma unroll
    for (int mt = 0; mt < 2; mt++) {
#pragma unroll
        for (int nt = 0; nt < 8; nt++) {
            const int gr0 = m0 + wm + mt * 16 + (lane >> 2);
            const int gc = n0 + wn + nt * 8 + (lane & 3) * 2;
            *(float2*)&Cout[(size_t)gr0 * DD + gc] =
                make_float2(c[mt][nt][0], c[mt][nt][1]);
            *(float2*)&Cout[(size_t)(gr0 + 8) * DD + gc] =
                make_float2(c[mt][nt][2], c[mt][nt][3]);
        }
    }
}

// ---------------------------------------------------------------------------
// Gate: a = 1 - sigmoid(zpre+bz), b = sigmoid(..)*tanh(hpre+bh)
// ---------------------------------------------------------------------------
__global__ void gate_kernel(const float* __restrict__ bz,
                            const float* __restrict__ bh) {
    const size_t idx = (size_t)blockIdx.x * 256 + threadIdx.x;  // float4 units
    const int d0 = (idx & 63) * 4;
    const float4 z4 = ((const float4*)g_zpre)[idx];
    const float4 h4 = ((const float4*)g_hpre)[idx];
    const float4 bz4 = *(const float4*)&bz[d0];
    const float4 bh4 = *(const float4*)&bh[d0];
    const float* zp = &z4.x;
    const float* hp = &h4.x;
    const float* bzp = &bz4.x;
    const float* bhp = &bh4.x;
    float4 av, bv;
    float* avp = &av.x;
    float* bvp = &bv.x;
#pragma unroll
    for (int j = 0; j < 4; j++) {
        const float z = fast_sigmoid(zp[j] + bzp[j]);
        const float t = fast_tanh(hp[j] + bhp[j]);
        avp[j] = 1.0f - z;
        bvp[j] = z * t;
    }
    ((float4*)g_a)[idx] = av;
    ((float4*)g_b)[idx] = bv;
}

// ---------------------------------------------------------------------------
// Layer-0 folding + conversions
// ---------------------------------------------------------------------------
__global__ void fold_wz_kernel(const float* __restrict__ question,
                               const float* __restrict__ Wz,
                               float* __restrict__ Wzp) {
    const int k = blockIdx.x, n = threadIdx.x;
    Wzp[k * DD + n] = question[k] * Wz[k * DD + n];
}
__global__ void fold_ch_kernel(const float* __restrict__ question,
                               const float* __restrict__ Whbot,
                               const float* __restrict__ bh,
                               float* __restrict__ ch) {
    const int n = threadIdx.x;
    float s = bh[n];
    for (int k = 0; k < DD; k++) s = fmaf(question[k], Whbot[k * DD + n], s);
    ch[n] = s;
}
// W [K][256] fp32 -> hi/lo [256][K] bf16 (transpose + split). grid=K, block=256.
__global__ void convT_kernel(const float* __restrict__ W, bf16* __restrict__ oh,
                             bf16* __restrict__ ol, int K) {
    const int k = blockIdx.x, n = threadIdx.x;
    const float v = W[k * DD + n];
    const bf16 h = __float2bfloat16(v);
    oh[(size_t)n * K + k] = h;
    ol[(size_t)n * K + k] = __float2bfloat16(v - __bfloat162float(h));
}
__global__ void split_x_kernel(const float* __restrict__ story) {
    const int idx = blockIdx.x * blockDim.x + threadIdx.x;
    const int t = idx >> 8, d = idx & 255;
    const float v = story[idx];
    const bf16 h = __float2bfloat16(v);
    g_xcat_h[(size_t)t * 512 + d] = h;
    g_xcat_l[(size_t)t * 512 + d] = __float2bfloat16(v - __bfloat162float(h));
}

// ---------------------------------------------------------------------------
// Scans (3-pass chunked linear recurrence; channel = threadIdx.x)
// ---------------------------------------------------------------------------
template <int REV>
__global__ void scan1_kernel() {
    const int c = blockIdx.x, d = threadIdx.x;
    float Ar = 1.0f, Br = 0.0f;
    const int base = c * CH;
#pragma unroll 4
    for (int i = 0; i < CH; i++) {
        const int t = base + (REV ? (CH - 1 - i) : i);
        const float a = g_a[(size_t)t * DD + d];
        const float b = g_b[(size_t)t * DD + d];
        Br = fmaf(a, Br, b);
        Ar *= a;
    }
    g_Aagg[c * DD + d] = Ar;
    g_Bagg[c * DD + d] = Br;
}

#define S2_BATCH 16
template <int REV>
__global__ void scan2_kernel() {
    const int d = blockIdx.x * 32 + threadIdx.x;
    float h = 0.0f;
    for (int ci0 = 0; ci0 < NC; ci0 += S2_BATCH) {
        float A[S2_BATCH], B[S2_BATCH];
#pragma unroll
        for (int j = 0; j < S2_BATCH; j++) {
            const int c = REV ? (NC - 1 - (ci0 + j)) : (ci0 + j);
            A[j] = g_Aagg[c * DD + d];
            B[j] = g_Bagg[c * DD + d];
        }
#pragma unroll
        for (int j = 0; j < S2_BATCH; j++) {
            const int c = REV ? (NC - 1 - (ci0 + j)) : (ci0 + j);
            g_pref[c * DD + d] = h;
            h = fmaf(A[j], h, B[j]);
        }
    }
}

__global__ void scan3_fwd_kernel() {
    const int c = blockIdx.x, d = threadIdx.x;
    float h = g_pref[c * DD + d];
    const int base = c * CH;
#pragma unroll 4
    for (int i = 0; i < CH; i++) {
        const int t = base + i;
        h = fmaf(g_a[(size_t)t * DD + d], h, g_b[(size_t)t * DD + d]);
        g_hf[(size_t)t * DD + d] = h;
    }
}

// Backward scan fused with next-layer operand prep:
//   q = h_bwd + h_fwd -> xcat[:,256+d] hi/lo ; xq = story*q -> xq hi/lo
__global__ void scan3_bwd_conv_kernel(const float* __restrict__ story) {
    const int c = blockIdx.x, d = threadIdx.x;
    float h = g_pref[c * DD + d];
    const int base = c * CH;
#pragma unroll 4
    for (int i = CH - 1; i >= 0; i--) {
        const int t = base + i;
        h = fmaf(g_a[(size_t)t * DD + d], h, g_b[(size_t)t * DD + d]);
        const float q = h + g_hf[(size_t)t * DD + d];
        const bf16 qh = __float2bfloat16(q);
        g_xcat_h[(size_t)t * 512 + 256 + d] = qh;
        g_xcat_l[(size_t)t * 512 + 256 + d] =
            __float2bfloat16(q - __bfloat162float(qh));
        const float p = story[(size_t)t * DD + d] * q;
        const bf16 ph = __float2bfloat16(p);
        g_xq_h[(size_t)t * DD + d] = ph;
        g_xq_l[(size_t)t * DD + d] =
            __float2bfloat16(p - __bfloat162float(ph));
    }
}

__global__ void final_kernel(float* __restrict__ out) {
    const int d = blockIdx.x * 32 + threadIdx.x;
    float h = 0.0f;
    for (int c0 = 0; c0 < NC; c0 += S2_BATCH) {
        float A[S2_BATCH], B[S2_BATCH];
#pragma unroll
        for (int j = 0; j < S2_BATCH; j++) {
            A[j] = g_Aagg[(c0 + j) * DD + d];
            B[j] = g_Bagg[(c0 + j) * DD + d];
        }
#pragma unroll
        for (int j = 0; j < S2_BATCH; j++) h = fmaf(A[j], h, B[j]);
    }
    out[d] = h;
}

// ---------------------------------------------------------------------------
extern "C" void kernel_launch(void* const* d_in, const int* in_sizes, int n_in,
                              void* d_out, int out_size) {
    const float* story = (const float*)d_in[0];
    const float* question = (const float*)d_in[1];
    const float* Wzf = (const float*)d_in[2];
    const float* bzf = (const float*)d_in[3];
    const float* Whf = (const float*)d_in[4];
    const float* bhf = (const float*)d_in[5];
    const float* Wzb = (const float*)d_in[6];
    const float* bzb = (const float*)d_in[7];
    const float* Whb = (const float*)d_in[8];
    const float* bhb = (const float*)d_in[9];
    float* out = (float*)d_out;

    cudaFuncSetAttribute(qrn_gemm_mma,
                         cudaFuncAttributeMaxDynamicSharedMemorySize, GEMM_SMEM);

#define SYM(v, s) void* v; cudaGetSymbolAddress(&v, s)
    SYM(pWz0f, g_Wz0f); SYM(pch0f, g_ch0f);
    SYM(pWz0b, g_Wz0b); SYM(pch0b, g_ch0b);
    SYM(pXh, g_xcat_h); SYM(pXl, g_xcat_l);
    SYM(pQh, g_xq_h);   SYM(pQl, g_xq_l);
    SYM(pZp, g_zpre);   SYM(pHp, g_hpre);
    SYM(pWz0fTh, g_Wz0fT_h); SYM(pWz0fTl, g_Wz0fT_l);
    SYM(pWz0bTh, g_Wz0bT_h); SYM(pWz0bTl, g_Wz0bT_l);
    SYM(pWt0fTh, g_Wt0fT_h); SYM(pWt0fTl, g_Wt0fT_l);
    SYM(pWt0bTh, g_Wt0bT_h); SYM(pWt0bTl, g_Wt0bT_l);
    SYM(pWzTh, g_WzT_h); SYM(pWzTl, g_WzT_l);
    SYM(pWhTh, g_WhT_h); SYM(pWhTl, g_WhT_l);
#undef SYM
#define BF(p) ((bf16*)(p))
#define F32(p) ((float*)(p))

    // ---- folding + conversions ----
    fold_wz_kernel<<<DD, DD>>>(question, Wzf, F32(pWz0f));
    fold_ch_kernel<<<1, DD>>>(question, Whf + DD * DD, bhf, F32(pch0f));
    fold_wz_kernel<<<DD, DD>>>(question, Wzb, F32(pWz0b));
    fold_ch_kernel<<<1, DD>>>(question, Whb + DD * DD, bhb, F32(pch0b));

    convT_kernel<<<DD, DD>>>(F32(pWz0f), BF(pWz0fTh), BF(pWz0fTl), DD);
    convT_kernel<<<DD, DD>>>(F32(pWz0b), BF(pWz0bTh), BF(pWz0bTl), DD);
    convT_kernel<<<DD, DD>>>(Whf, BF(pWt0fTh), BF(pWt0fTl), DD);
    convT_kernel<<<DD, DD>>>(Whb, BF(pWt0bTh), BF(pWt0bTl), DD);
    convT_kernel<<<DD, DD>>>(Wzf + 1 * DD * DD, BF(pWzTh) + 0 * DD * DD,
                             BF(pWzTl) + 0 * DD * DD, DD);
    convT_kernel<<<DD, DD>>>(Wzf + 2 * DD * DD, BF(pWzTh) + 1 * DD * DD,
                             BF(pWzTl) + 1 * DD * DD, DD);
    convT_kernel<<<DD, DD>>>(Wzb + 1 * DD * DD, BF(pWzTh) + 2 * DD * DD,
                             BF(pWzTl) + 2 * DD * DD, DD);
    convT_kernel<<<512, DD>>>(Whf + 1 * 2 * DD * DD, BF(pWhTh) + 0 * DD * 512,
                              BF(pWhTl) + 0 * DD * 512, 512);
    convT_kernel<<<512, DD>>>(Whf + 2 * 2 * DD * DD, BF(pWhTh) + 1 * DD * 512,
                              BF(pWhTl) + 1 * DD * 512, 512);
    convT_kernel<<<512, DD>>>(Whb + 1 * 2 * DD * DD, BF(pWhTh) + 2 * DD * 512,
                              BF(pWhTl) + 2 * DD * 512, 512);
    split_x_kernel<<<TT * DD / 256, 256>>>(story);

    const dim3 gg(TT / 128, 2);
    const int GATE_G = TT * DD / 4 / 256;

    // ---- layer 0 fwd (A = x slice of xcat, lda=512, K=256) ----
    qrn_gemm_mma<<<gg, 256, GEMM_SMEM>>>(BF(pXh), BF(pXl), 512, 256,
                                         BF(pWz0fTh), BF(pWz0fTl), F32(pZp));
    qrn_gemm_mma<<<gg, 256, GEMM_SMEM>>>(BF(pXh), BF(pXl), 512, 256,
                                         BF(pWt0fTh), BF(pWt0fTl), F32(pHp));
    gate_kernel<<<GATE_G, 256>>>(bzf, F32(pch0f));
    scan1_kernel<0><<<NC, DD>>>();
    scan2_kernel<0><<<8, 32>>>();
    scan3_fwd_kernel<<<NC, DD>>>();
    // ---- layer 0 bwd ----
    qrn_gemm_mma<<<gg, 256, GEMM_SMEM>>>(BF(pXh), BF(pXl), 512, 256,
                                         BF(pWz0bTh), BF(pWz0bTl), F32(pZp));
    qrn_gemm_mma<<<gg, 256, GEMM_SMEM>>>(BF(pXh), BF(pXl), 512, 256,
                                         BF(pWt0bTh), BF(pWt0bTl), F32(pHp));
    gate_kernel<<<GATE_G, 256>>>(bzb, F32(pch0b));
    scan1_kernel<1><<<NC, DD>>>();
    scan2_kernel<1><<<8, 32>>>();
    scan3_bwd_conv_kernel<<<NC, DD>>>(story);  // q, xq hi/lo for layer 1

    // ---- layer 1 fwd ----
    qrn_gemm_mma<<<gg, 256, GEMM_SMEM>>>(
        BF(pQh), BF(pQl), 256, 256,
        BF(pWzTh) + 0 * DD * DD, BF(pWzTl) + 0 * DD * DD, F32(pZp));
    qrn_gemm_mma<<<gg, 256, GEMM_SMEM>>>(
        BF(pXh), BF(pXl), 512, 512,
        BF(pWhTh) + 0 * DD * 512, BF(pWhTl) + 0 * DD * 512, F32(pHp));
    gate_kernel<<<GATE_G, 256>>>(bzf + DD, bhf + DD);
    scan1_kernel<0><<<NC, DD>>>();
    scan2_kernel<0><<<8, 32>>>();
    scan3_fwd_kernel<<<NC, DD>>>();
    // ---- layer 1 bwd ----
    qrn_gemm_mma<<<gg, 256, GEMM_SMEM>>>(
        BF(pQh), BF(pQl), 256, 256,
        BF(pWzTh) + 2 * DD * DD, BF(pWzTl) + 2 * DD * DD, F32(pZp));
    qrn_gemm_mma<<<gg, 256, GEMM_SMEM>>>(
        BF(pXh), BF(pXl), 512, 512,
        BF(pWhTh) + 2 * DD * 512, BF(pWhTl) + 2 * DD * 512, F32(pHp));
    gate_kernel<<<GATE_G, 256>>>(bzb + DD, bhb + DD);
    scan1_kernel<1><<<NC, DD>>>();
    scan2_kernel<1><<<8, 32>>>();
    scan3_bwd_conv_kernel<<<NC, DD>>>(story);  // q, xq for layer 2

    // ---- layer 2 fwd (only h_fwd[T-1] needed) ----
    qrn_gemm_mma<<<gg, 256, GEMM_SMEM>>>(
        BF(pQh), BF(pQl), 256, 256,
        BF(pWzTh) + 1 * DD * DD, BF(pWzTl) + 1 * DD * DD, F32(pZp));
    qrn_gemm_mma<<<gg, 256, GEMM_SMEM>>>(
        BF(pXh), BF(pXl), 512, 512,
        BF(pWhTh) + 1 * DD * 512, BF(pWhTl) + 1 * DD * 512, F32(pHp));
    gate_kernel<<<GATE_G, 256>>>(bzf + 2 * DD, bhf + 2 * DD);
    scan1_kernel<0><<<NC, DD>>>();
    final_kernel<<<8, 32>>>(out);
}